// round 9
// baseline (speedup 1.0000x reference)
#include <cuda_runtime.h>
#include <cuda_bf16.h>
#include <math.h>
#include <stdint.h>

#define BB   2
#define SS   2048
#define DM   768
#define NH   12
#define DK   64
#define BHT  (BB*NH)      // 24
#define MTOT (BB*SS)      // 4096

// ---------------- scratch (device globals: no allocations allowed) ----------
// pre-split inputs (hi/lo bf16)
__device__ __nv_bfloat16 g_qxh[MTOT * DM], g_qxl[MTOT * DM];
__device__ __nv_bfloat16 g_kxh[MTOT * DM], g_kxl[MTOT * DM];
__device__ __nv_bfloat16 g_vxh[MTOT * DM], g_vxl[MTOT * DM];
__device__ __nv_bfloat16 g_wkh[DM * DM],   g_wkl[DM * DM];
__device__ __nv_bfloat16 g_woh[DM * DM],   g_wol[DM * DM];
// projected q/k/v in head layout [b*H+h][s][d], hi/lo bf16
__device__ __nv_bfloat16 g_qhh[BHT * SS * DK], g_qhl[BHT * SS * DK];
__device__ __nv_bfloat16 g_khh[BHT * SS * DK], g_khl[BHT * SS * DK];
__device__ __nv_bfloat16 g_vhh[BHT * SS * DK], g_vhl[BHT * SS * DK];
// attention output (concat layout [b][s][h*64+d]), hi/lo bf16
__device__ __nv_bfloat16 g_ch[BB * SS * DM], g_cl[BB * SS * DM];

// ============================= helpers =====================================
__device__ __forceinline__ uint32_t smem_u32(const void* p) {
    uint32_t a;
    asm("{ .reg .u64 t; cvta.to.shared.u64 t, %1; cvt.u32.u64 %0, t; }"
        : "=r"(a) : "l"(p));
    return a;
}
__device__ __forceinline__ void ldsm_x4(uint32_t* r, uint32_t addr) {
    asm volatile("ldmatrix.sync.aligned.m8n8.x4.shared.b16 {%0,%1,%2,%3}, [%4];"
                 : "=r"(r[0]), "=r"(r[1]), "=r"(r[2]), "=r"(r[3]) : "r"(addr));
}
__device__ __forceinline__ void ldsm_x4_t(uint32_t* r, uint32_t addr) {
    asm volatile("ldmatrix.sync.aligned.m8n8.x4.trans.shared.b16 {%0,%1,%2,%3}, [%4];"
                 : "=r"(r[0]), "=r"(r[1]), "=r"(r[2]), "=r"(r[3]) : "r"(addr));
}
// D = A(16x16 bf16, row) @ B(16x8 bf16, col) + C, fp32 accum
__device__ __forceinline__ void mma_bf16(float* d, const uint32_t* a,
                                         const uint32_t* b) {
    asm volatile(
        "mma.sync.aligned.m16n8k16.row.col.f32.bf16.bf16.f32 "
        "{%0,%1,%2,%3}, {%4,%5,%6,%7}, {%8,%9}, {%0,%1,%2,%3};"
        : "+f"(d[0]), "+f"(d[1]), "+f"(d[2]), "+f"(d[3])
        : "r"(a[0]), "r"(a[1]), "r"(a[2]), "r"(a[3]),
          "r"(b[0]), "r"(b[1]));
}
__device__ __forceinline__ uint32_t pack_bf16_hi(float x, float y) {
    __nv_bfloat162 h = __floats2bfloat162_rn(x, y);
    return *reinterpret_cast<uint32_t*>(&h);
}
__device__ __forceinline__ void split2(float x, float y, uint32_t& hi, uint32_t& lo) {
    uint32_t h = pack_bf16_hi(x, y);
    float hx = __bfloat162float(__ushort_as_bfloat16((uint16_t)h));
    float hy = __bfloat162float(__ushort_as_bfloat16((uint16_t)(h >> 16)));
    hi = h;
    lo = pack_bf16_hi(x - hx, y - hy);
}

// ---------------------------------------------------------------------------
// Pre-pass: split fp32 array into bf16 hi + lo arrays. n4 = n/4.
// ---------------------------------------------------------------------------
__global__ __launch_bounds__(256)
void split_fp32(const float* __restrict__ in,
                __nv_bfloat16* __restrict__ hi,
                __nv_bfloat16* __restrict__ lo, int n4)
{
    int i = blockIdx.x * blockDim.x + threadIdx.x;
    if (i >= n4) return;
    float4 v = reinterpret_cast<const float4*>(in)[i];
    uint32_t h0, l0, h1, l1;
    split2(v.x, v.y, h0, l0);
    split2(v.z, v.w, h1, l1);
    reinterpret_cast<uint2*>(hi)[i] = make_uint2(h0, h1);
    reinterpret_cast<uint2*>(lo)[i] = make_uint2(l0, l1);
}

// ---------------------------------------------------------------------------
// HMMA GEMM on pre-split bf16 operands:
//   Y = A @ B^T + bias,  A = Ah+Al [M,768], B = Bh+Bl [768,768]
// 3-term: Ah@Bh + Ah@Bl + Al@Bh. CTA 128x128, 8 warps (2x4), warp 64x32.
// HEAD_OUT: write bf16 hi/lo pair to head layout; else fp32 row-major.
// ---------------------------------------------------------------------------
#define PADK 40

template <bool HEAD_OUT>
__global__ __launch_bounds__(256)
void gemm_bf16(const __nv_bfloat16* __restrict__ Ah,
               const __nv_bfloat16* __restrict__ Al,
               const __nv_bfloat16* __restrict__ Bh,
               const __nv_bfloat16* __restrict__ Bl,
               const float* __restrict__ bias,
               float* __restrict__ Yf,
               __nv_bfloat16* __restrict__ Yh,
               __nv_bfloat16* __restrict__ Yl)
{
    __shared__ __nv_bfloat16 AHs[128][PADK];
    __shared__ __nv_bfloat16 ALs[128][PADK];
    __shared__ __nv_bfloat16 BHs[128][PADK];
    __shared__ __nv_bfloat16 BLs[128][PADK];

    const int tid = threadIdx.x;
    const int wid = tid >> 5;
    const int lid = tid & 31;
    const int m0  = blockIdx.y * 128;
    const int n0  = blockIdx.x * 128;
    const int wm  = (wid >> 2) * 64;
    const int wn  = (wid & 3) * 32;

    float acc[4][4][4];
    #pragma unroll
    for (int i = 0; i < 4; i++)
        #pragma unroll
        for (int j = 0; j < 4; j++)
            #pragma unroll
            for (int t = 0; t < 4; t++) acc[i][j][t] = 0.0f;

    for (int k0 = 0; k0 < DM; k0 += 32) {
        // ---- pure copy fill: 8x LDG.128 + 8x STS.128 per thread ----
        #pragma unroll
        for (int r = 0; r < 2; r++) {
            int idx = tid + 256 * r;      // uint4 slot 0..511
            int row = idx >> 2;           // 4 uint4 per row (32 halves)
            int cc  = (idx & 3) * 8;      // half offset
            size_t ga = (size_t)(m0 + row) * DM + k0 + cc;
            size_t gb = (size_t)(n0 + row) * DM + k0 + cc;
            *reinterpret_cast<uint4*>(&AHs[row][cc]) = *reinterpret_cast<const uint4*>(&Ah[ga]);
            *reinterpret_cast<uint4*>(&ALs[row][cc]) = *reinterpret_cast<const uint4*>(&Al[ga]);
            *reinterpret_cast<uint4*>(&BHs[row][cc]) = *reinterpret_cast<const uint4*>(&Bh[gb]);
            *reinterpret_cast<uint4*>(&BLs[row][cc]) = *reinterpret_cast<const uint4*>(&Bl[gb]);
        }
        __syncthreads();

        #pragma unroll
        for (int kk = 0; kk < 2; kk++) {
            const int kc = kk * 16;

            uint32_t ah[4][4], al[4][4];
            {
                int arow = wm + (lid & 15);
                int acol = kc + (lid >> 4) * 8;
                #pragma unroll
                for (int i = 0; i < 4; i++) {
                    ldsm_x4(ah[i], smem_u32(&AHs[arow + i * 16][acol]));
                    ldsm_x4(al[i], smem_u32(&ALs[arow + i * 16][acol]));
                }
            }
            uint32_t bh[2][4], bl[2][4];
            {
                int brow = wn + (lid & 7) + (lid >> 4) * 8;
                int bcol = kc + ((lid >> 3) & 1) * 8;
                #pragma unroll
                for (int p = 0; p < 2; p++) {
                    ldsm_x4(bh[p], smem_u32(&BHs[brow + p * 16][bcol]));
                    ldsm_x4(bl[p], smem_u32(&BLs[brow + p * 16][bcol]));
                }
            }

            #pragma unroll
            for (int i = 0; i < 4; i++)
                #pragma unroll
                for (int j = 0; j < 4; j++) {
                    const uint32_t* bhj = &bh[j >> 1][(j & 1) * 2];
                    const uint32_t* blj = &bl[j >> 1][(j & 1) * 2];
                    mma_bf16(acc[i][j], ah[i], bhj);
                    mma_bf16(acc[i][j], ah[i], blj);
                    mma_bf16(acc[i][j], al[i], bhj);
                }
        }
        __syncthreads();
    }

    // ---- epilogue ----
    const int fr = lid >> 2;
    const int fc = (lid & 3) * 2;
    #pragma unroll
    for (int j = 0; j < 4; j++) {
        const int n = n0 + wn + j * 8 + fc;
        const float b0 = bias[n];
        const float b1 = bias[n + 1];
        #pragma unroll
        for (int i = 0; i < 4; i++) {
            #pragma unroll
            for (int half = 0; half < 2; half++) {
                const int m = m0 + wm + i * 16 + fr + half * 8;
                float vx = acc[i][j][half * 2 + 0] + b0;
                float vy = acc[i][j][half * 2 + 1] + b1;
                if (HEAD_OUT) {
                    const int b  = m >> 11;
                    const int s  = m & (SS - 1);
                    const int h  = n >> 6;
                    const int dk = n & 63;
                    size_t off = (((size_t)(b * NH + h) * SS) + s) * DK + dk;
                    uint32_t hi, lo;
                    split2(vx, vy, hi, lo);
                    *reinterpret_cast<uint32_t*>(&Yh[off]) = hi;
                    *reinterpret_cast<uint32_t*>(&Yl[off]) = lo;
                } else {
                    float2 val; val.x = vx; val.y = vy;
                    *reinterpret_cast<float2*>(&Yf[(size_t)m * DM + n]) = val;
                }
            }
        }
    }
}

// ---------------------------------------------------------------------------
// HMMA flash attention on pre-split bf16 q/k/v.
// CTA = (bh, 64 q-rows), 4 warps, 2 CTAs/SM. Warp = 16 q-rows.
// Inner loop has ZERO fp32->bf16 conversions for K/V (pure LDG->STS fill).
// Writes concat output as bf16 hi/lo for the final GEMM.
// ---------------------------------------------------------------------------
#define PADH 72   // halves per smem row (144B stride -> conflict-free ldmatrix)

__global__ __launch_bounds__(128, 2)
void flash_mma2(const __nv_bfloat16* __restrict__ Qhg,
                const __nv_bfloat16* __restrict__ Qlg,
                const __nv_bfloat16* __restrict__ Khg,
                const __nv_bfloat16* __restrict__ Klg,
                const __nv_bfloat16* __restrict__ Vhg,
                const __nv_bfloat16* __restrict__ Vlg,
                __nv_bfloat16* __restrict__ Ch,
                __nv_bfloat16* __restrict__ Cl)
{
    __shared__ __align__(16) char raw[4 * 64 * PADH * 2];   // 36864 B

    __nv_bfloat16 (*Qh_s)[PADH] = reinterpret_cast<__nv_bfloat16(*)[PADH]>(raw);
    __nv_bfloat16 (*Ql_s)[PADH] = reinterpret_cast<__nv_bfloat16(*)[PADH]>(raw + 9216);
    __nv_bfloat16 (*Kh_s)[PADH] = reinterpret_cast<__nv_bfloat16(*)[PADH]>(raw);
    __nv_bfloat16 (*Kl_s)[PADH] = reinterpret_cast<__nv_bfloat16(*)[PADH]>(raw + 9216);
    __nv_bfloat16 (*Vh_s)[PADH] = reinterpret_cast<__nv_bfloat16(*)[PADH]>(raw + 18432);
    __nv_bfloat16 (*Vl_s)[PADH] = reinterpret_cast<__nv_bfloat16(*)[PADH]>(raw + 27648);

    const int tid = threadIdx.x;
    const int wid = tid >> 5;          // 0..3
    const int lid = tid & 31;
    const int bh  = blockIdx.y;
    const int q0  = blockIdx.x * 64;

    const size_t base = (size_t)bh * SS * DK;
    const __nv_bfloat16* Qhb = Qhg + base;
    const __nv_bfloat16* Qlb = Qlg + base;
    const __nv_bfloat16* Khb = Khg + base;
    const __nv_bfloat16* Klb = Klg + base;
    const __nv_bfloat16* Vhb = Vhg + base;
    const __nv_bfloat16* Vlb = Vlg + base;

    // ---- prologue: copy Q tile (64x64 halves, hi+lo) into smem ----
    #pragma unroll
    for (int r = 0; r < 4; r++) {
        int idx = tid + 128 * r;        // uint4 slot 0..511
        int row = idx >> 3;             // 8 uint4 per row (64 halves)
        int cc  = (idx & 7) * 8;
        size_t g = (size_t)(q0 + row) * DK + cc;
        *reinterpret_cast<uint4*>(&Qh_s[row][cc]) = *reinterpret_cast<const uint4*>(&Qhb[g]);
        *reinterpret_cast<uint4*>(&Ql_s[row][cc]) = *reinterpret_cast<const uint4*>(&Qlb[g]);
    }
    __syncthreads();

    // ---- hoist Q A-fragments (4 k-steps, hi + lo) into registers ----
    uint32_t qfh[4][4], qfl[4][4];
    {
        int arow = wid * 16 + (lid & 15);
        int acol = (lid >> 4) * 8;
        #pragma unroll
        for (int ks = 0; ks < 4; ks++) {
            ldsm_x4(qfh[ks], smem_u32(&Qh_s[arow][ks * 16 + acol]));
            ldsm_x4(qfl[ks], smem_u32(&Ql_s[arow][ks * 16 + acol]));
        }
    }

    float m_i[2], l_i[2], oacc[8][4];
    #pragma unroll
    for (int h2 = 0; h2 < 2; h2++) { m_i[h2] = -INFINITY; l_i[h2] = 0.0f; }
    #pragma unroll
    for (int j = 0; j < 8; j++)
        #pragma unroll
        for (int t = 0; t < 4; t++) oacc[j][t] = 0.0f;

    const float scale = 0.125f;   // 1/sqrt(Dk)

    for (int kv0 = 0; kv0 < SS; kv0 += 64) {
        __syncthreads();   // previous readers done (Q frags live in regs)

        // ---- copy K,V tiles (hi+lo): pure LDG->STS ----
        #pragma unroll
        for (int r = 0; r < 4; r++) {
            int idx = tid + 128 * r;
            int row = idx >> 3;
            int cc  = (idx & 7) * 8;
            size_t g = (size_t)(kv0 + row) * DK + cc;
            *reinterpret_cast<uint4*>(&Kh_s[row][cc]) = *reinterpret_cast<const uint4*>(&Khb[g]);
            *reinterpret_cast<uint4*>(&Kl_s[row][cc]) = *reinterpret_cast<const uint4*>(&Klb[g]);
            *reinterpret_cast<uint4*>(&Vh_s[row][cc]) = *reinterpret_cast<const uint4*>(&Vhb[g]);
            *reinterpret_cast<uint4*>(&Vl_s[row][cc]) = *reinterpret_cast<const uint4*>(&Vlb[g]);
        }
        __syncthreads();

        // ---- S = Q @ K^T (16 x 64 per warp) ----
        float sacc[8][4];
        #pragma unroll
        for (int j = 0; j < 8; j++)
            #pragma unroll
            for (int t = 0; t < 4; t++) sacc[j][t] = 0.0f;

        #pragma unroll
        for (int ks = 0; ks < 4; ks++) {
            #pragma unroll
            for (int jj = 0; jj < 4; jj++) {
                int brow = jj * 16 + (lid & 7) + ((lid >> 4) << 3);
                int bcol = ks * 16 + ((lid >> 3) & 1) * 8;
                uint32_t kb_h[4], kb_l[4];
                ldsm_x4(kb_h, smem_u32(&Kh_s[brow][bcol]));
                ldsm_x4(kb_l, smem_u32(&Kl_s[brow][bcol]));
                #pragma unroll
                for (int p = 0; p < 2; p++) {
                    float* d = sacc[jj * 2 + p];
                    mma_bf16(d, qfh[ks], &kb_h[p * 2]);
                    mma_bf16(d, qfh[ks], &kb_l[p * 2]);
                    mma_bf16(d, qfl[ks], &kb_h[p * 2]);
                }
            }
        }

        // ---- online softmax (rows fr, fr+8; 4-lane groups share a row) ----
        #pragma unroll
        for (int h2 = 0; h2 < 2; h2++) {
            const int basei = h2 * 2;
            float mx = -INFINITY;
            #pragma unroll
            for (int j = 0; j < 8; j++) {
                sacc[j][basei]     *= scale;
                sacc[j][basei + 1] *= scale;
                mx = fmaxf(mx, fmaxf(sacc[j][basei], sacc[j][basei + 1]));
            }
            mx = fmaxf(mx, __shfl_xor_sync(0xffffffffu, mx, 1));
            mx = fmaxf(mx, __shfl_xor_sync(0xffffffffu, mx, 2));

            float mn    = fmaxf(m_i[h2], mx);
            float alpha = __expf(m_i[h2] - mn);
            m_i[h2] = mn;

            float rs = 0.0f;
            #pragma unroll
            for (int j = 0; j < 8; j++) {
                float p0 = __expf(sacc[j][basei]     - mn);
                float p1 = __expf(sacc[j][basei + 1] - mn);
                sacc[j][basei]     = p0;
                sacc[j][basei + 1] = p1;
                rs += p0 + p1;
            }
            rs += __shfl_xor_sync(0xffffffffu, rs, 1);
            rs += __shfl_xor_sync(0xffffffffu, rs, 2);

            l_i[h2] = l_i[h2] * alpha + rs;
            #pragma unroll
            for (int j = 0; j < 8; j++) {
                oacc[j][basei]     *= alpha;
                oacc[j][basei + 1] *= alpha;
            }
        }

        // ---- O += P @ V (P regs -> bf16 split; V^T frags via ldmatrix.trans)
        #pragma unroll
        for (int t = 0; t < 4; t++) {
            uint32_t pah[4], pal[4];
            split2(sacc[2 * t][0],     sacc[2 * t][1],     pah[0], pal[0]);
            split2(sacc[2 * t][2],     sacc[2 * t][3],     pah[1], pal[1]);
            split2(sacc[2 * t + 1][0], sacc[2 * t + 1][1], pah[2], pal[2]);
            split2(sacc[2 * t + 1][2], sacc[2 * t + 1][3], pah[3], pal[3]);

            const int vrow  = t * 16 + (lid & 15);
            const int vcolw = (lid >> 4) << 3;
            #pragma unroll
            for (int dd = 0; dd < 4; dd++) {         // d-col groups of 16
                uint32_t vh4[4], vl4[4];
                ldsm_x4_t(vh4, smem_u32(&Vh_s[vrow][dd * 16 + vcolw]));
                ldsm_x4_t(vl4, smem_u32(&Vl_s[vrow][dd * 16 + vcolw]));
                float* d0 = oacc[dd * 2 + 0];
                float* d1 = oacc[dd * 2 + 1];
                mma_bf16(d0, pah, &vh4[0]);
                mma_bf16(d0, pal, &vh4[0]);
                mma_bf16(d0, pah, &vl4[0]);
                mma_bf16(d1, pah, &vh4[2]);
                mma_bf16(d1, pal, &vh4[2]);
                mma_bf16(d1, pah, &vl4[2]);
            }
        }
    }

    // ---- epilogue: normalize + split + write concat hi/lo [b][s][h*64+d] ----
    const int b    = bh / NH;
    const int head = bh % NH;
    const int fr   = lid >> 2;
    const int fc   = (lid & 3) * 2;
    #pragma unroll
    for (int h2 = 0; h2 < 2; h2++) {
        const float inv = 1.0f / l_i[h2];
        const int srow  = q0 + wid * 16 + fr + 8 * h2;
        const size_t roff = ((size_t)(b * SS + srow)) * DM + head * DK;
        #pragma unroll
        for (int j = 0; j < 8; j++) {
            float vx = oacc[j][h2 * 2 + 0] * inv;
            float vy = oacc[j][h2 * 2 + 1] * inv;
            uint32_t hi, lo;
            split2(vx, vy, hi, lo);
            *reinterpret_cast<uint32_t*>(&Ch[roff + j * 8 + fc]) = hi;
            *reinterpret_cast<uint32_t*>(&Cl[roff + j * 8 + fc]) = lo;
        }
    }
}

// ---------------------------------------------------------------------------
extern "C" void kernel_launch(void* const* d_in, const int* in_sizes, int n_in,
                              void* d_out, int out_size)
{
    const float* q  = (const float*)d_in[0];
    const float* k  = (const float*)d_in[1];
    const float* v  = (const float*)d_in[2];
    const float* Wk = (const float*)d_in[3];
    const float* bk = (const float*)d_in[4];
    const float* Wo = (const float*)d_in[5];
    const float* bo = (const float*)d_in[6];
    float* out = (float*)d_out;

    __nv_bfloat16 *qxh, *qxl, *kxh, *kxl, *vxh, *vxl, *wkh, *wkl, *woh, *wol;
    __nv_bfloat16 *qhh, *qhl, *khh, *khl, *vhh, *vhl, *ch, *cl;
    cudaGetSymbolAddress((void**)&qxh, g_qxh);  cudaGetSymbolAddress((void**)&qxl, g_qxl);
    cudaGetSymbolAddress((void**)&kxh, g_kxh);  cudaGetSymbolAddress((void**)&kxl, g_kxl);
    cudaGetSymbolAddress((void**)&vxh, g_vxh);  cudaGetSymbolAddress((void**)&vxl, g_vxl);
    cudaGetSymbolAddress((void**)&wkh, g_wkh);  cudaGetSymbolAddress((void**)&wkl, g_wkl);
    cudaGetSymbolAddress((void**)&woh, g_woh);  cudaGetSymbolAddress((void**)&wol, g_wol);
    cudaGetSymbolAddress((void**)&qhh, g_qhh);  cudaGetSymbolAddress((void**)&qhl, g_qhl);
    cudaGetSymbolAddress((void**)&khh, g_khh);  cudaGetSymbolAddress((void**)&khl, g_khl);
    cudaGetSymbolAddress((void**)&vhh, g_vhh);  cudaGetSymbolAddress((void**)&vhl, g_vhl);
    cudaGetSymbolAddress((void**)&ch,  g_ch);   cudaGetSymbolAddress((void**)&cl,  g_cl);

    // ---- pre-split inputs ----
    const int NX4 = MTOT * DM / 4;   // 786432
    const int NW4 = DM * DM / 4;     // 147456
    split_fp32<<<NX4 / 256, 256>>>(q,  qxh, qxl, NX4);
    split_fp32<<<NX4 / 256, 256>>>(k,  kxh, kxl, NX4);
    split_fp32<<<NX4 / 256, 256>>>(v,  vxh, vxl, NX4);
    split_fp32<<<NW4 / 256, 256>>>(Wk, wkh, wkl, NW4);
    split_fp32<<<NW4 / 256, 256>>>(Wo, woh, wol, NW4);

    dim3 gemm_grid(DM / 128, MTOT / 128);   // (6, 32)
    dim3 attn_grid(SS / 64, BHT);           // (32, 24)

    // 3 projections (all through Wk/bk -- faithful to the reference bug)
    gemm_bf16<true><<<gemm_grid, 256>>>(qxh, qxl, wkh, wkl, bk, nullptr, qhh, qhl);
    gemm_bf16<true><<<gemm_grid, 256>>>(kxh, kxl, wkh, wkl, bk, nullptr, khh, khl);
    gemm_bf16<true><<<gemm_grid, 256>>>(vxh, vxl, wkh, wkl, bk, nullptr, vhh, vhl);

    // attention (HMMA bf16 split, pre-packed operands)
    flash_mma2<<<attn_grid, 128>>>(qhh, qhl, khh, khl, vhh, vhl, ch, cl);

    // output projection
    gemm_bf16<false><<<gemm_grid, 256>>>(ch, cl, woh, wol, bo, out, nullptr, nullptr);
}